// round 2
// baseline (speedup 1.0000x reference)
#include <cuda_runtime.h>
#include <cuda_bf16.h>

#define NE 10000
#define NM 2048
#define D  128

// ---------------- device scratch (no allocations allowed) ----------------
__device__ signed char g_lev[(size_t)NE * NM];      // 20.48 MB: 0 = no edge, 1..5 = relation
__device__ float g_inv[NE * 5];                     // 1/cnt per (entity, relation)
__device__ float g_m1[NM * D];                      // relu(x_m @ root1 + b1)
__device__ float g_Z[(size_t)5 * NM * 256];         // [r][j][0:128]=x_m@W1[r+1], [128:256]=m1@W2[r+1]
__device__ float g_ebase[(size_t)NE * D];           // x_e @ root1 + b1 (pre-relu, pre-agg)

// ---------------- kernel 1: levels + inverse counts ----------------
__global__ void k_lev(const float* __restrict__ w) {
    int i = blockIdx.x;
    __shared__ int scnt[5];
    if (threadIdx.x < 5) scnt[threadIdx.x] = 0;
    __syncthreads();

    int cnt[5] = {0, 0, 0, 0, 0};
    const float* wr = w + (size_t)i * NM;
    signed char* lr = g_lev + (size_t)i * NM;
    for (int j = threadIdx.x; j < NM; j += 256) {
        float v = wr[j];
        int lv = (int)ceilf(v * 6.0f) - 1;      // matches jnp.ceil(w*6)-1 in f32
        int o = (lv >= 1 && lv <= 5) ? lv : 0;  // only relations 1..5 form edges
        lr[j] = (signed char)o;
        if (o) cnt[o - 1]++;
    }
    #pragma unroll
    for (int r = 0; r < 5; r++) {
        int v = cnt[r];
        #pragma unroll
        for (int off = 16; off; off >>= 1) v += __shfl_down_sync(0xffffffffu, v, off);
        if ((threadIdx.x & 31) == 0) atomicAdd(&scnt[r], v);
    }
    __syncthreads();
    if (threadIdx.x < 5) {
        int c = scnt[threadIdx.x];
        g_inv[i * 5 + threadIdx.x] = (c > 0) ? 1.0f / (float)c : 0.0f;
    }
}

// ---------------- kernel 2: m1 = relu(x_m @ root1 + b1), 8 rows/block ----------------
__global__ void k_m1(const float* __restrict__ xm, const float* __restrict__ root1,
                     const float* __restrict__ b1) {
    int j0 = blockIdx.x * 8;
    int c = threadIdx.x;
    __shared__ float xs[8][128];
    for (int t = c; t < 8 * 128; t += 128) xs[t >> 7][t & 127] = xm[(size_t)(j0 + (t >> 7)) * D + (t & 127)];
    __syncthreads();
    float a[8] = {0, 0, 0, 0, 0, 0, 0, 0};
    #pragma unroll 4
    for (int k = 0; k < 128; k++) {
        float wv = root1[k * D + c];
        #pragma unroll
        for (int e = 0; e < 8; e++) a[e] += xs[e][k] * wv;
    }
    float bb = b1[c];
    #pragma unroll
    for (int e = 0; e < 8; e++) g_m1[(size_t)(j0 + e) * D + c] = fmaxf(a[e] + bb, 0.0f);
}

// ---------------- kernel 3: ebase = x_e @ root1 + b1 (no relu), 8 rows/block ----------------
__global__ void k_ebase(const float* __restrict__ xe, const float* __restrict__ root1,
                        const float* __restrict__ b1) {
    int i0 = blockIdx.x * 8;
    int c = threadIdx.x;
    __shared__ float xs[8][128];
    for (int t = c; t < 8 * 128; t += 128) xs[t >> 7][t & 127] = xe[(size_t)(i0 + (t >> 7)) * D + (t & 127)];
    __syncthreads();
    float a[8] = {0, 0, 0, 0, 0, 0, 0, 0};
    #pragma unroll 4
    for (int k = 0; k < 128; k++) {
        float wv = root1[k * D + c];
        #pragma unroll
        for (int e = 0; e < 8; e++) a[e] += xs[e][k] * wv;
    }
    float bb = b1[c];
    #pragma unroll
    for (int e = 0; e < 8; e++) g_ebase[(size_t)(i0 + e) * D + c] = a[e] + bb;
}

// ---------------- kernel 4: Z[r][j][:] = [x_m@W1[r+1] | m1@W2[r+1]], 8 j/block ----------------
__global__ void k_Z(const float* __restrict__ xm, const float* __restrict__ W1,
                    const float* __restrict__ W2) {
    int ri = blockIdx.y;
    int j0 = blockIdx.x * 8;
    __shared__ float xs[8][128], ms[8][128];
    for (int t = threadIdx.x; t < 8 * 128; t += 256) {
        int e = t >> 7, k = t & 127;
        xs[e][k] = xm[(size_t)(j0 + e) * D + k];
        ms[e][k] = g_m1[(size_t)(j0 + e) * D + k];
    }
    __syncthreads();
    int c = threadIdx.x;
    int cc = c & 127;
    const float* W = ((c < 128) ? W1 : W2) + (size_t)(ri + 1) * D * D;
    const float(*S)[128] = (c < 128) ? xs : ms;
    float a[8] = {0, 0, 0, 0, 0, 0, 0, 0};
    #pragma unroll 4
    for (int k = 0; k < 128; k++) {
        float wv = W[k * D + cc];
        #pragma unroll
        for (int e = 0; e < 8; e++) a[e] += S[e][k] * wv;
    }
    #pragma unroll
    for (int e = 0; e < 8; e++) g_Z[((size_t)ri * NM + j0 + e) * 256 + c] = a[e];
}

// ---------------- kernel 5: main fused aggregation + both conv epilogues ----------------
// Block: 64 entities, 256 threads. Thread (pe=tid>>3, cg=tid&7) owns entities {2pe, 2pe+1},
// columns c = cg*4 + 32*k (k=0..7) of the 256-wide accumulator (conflict-free LDS.128).
constexpr int EB = 64;
constexpr int TJ = 32;
// smem: Zs 5*32*256 f32 (163840 B) | lev 64*32 B | inv 64*5 f32
constexpr int SM_ZS_F = 5 * TJ * 256;                      // floats
constexpr int SM_MAIN = SM_ZS_F * 4 + EB * TJ + EB * 5 * 4;

__global__ __launch_bounds__(256, 1) void k_main(const float* __restrict__ root2,
                                                 const float* __restrict__ b2,
                                                 float* __restrict__ out) {
    extern __shared__ float smem[];
    float* Zs = smem;
    signed char* lev_s = (signed char*)(smem + SM_ZS_F);
    float* inv_s = (float*)(lev_s + EB * TJ);

    int i0 = blockIdx.x * EB;
    int tid = threadIdx.x;
    int pe = tid >> 3, cg = tid & 7;
    int eA = pe * 2, eBt = pe * 2 + 1;

    for (int t = tid; t < EB * 5; t += 256) {
        int e = t / 5, r = t - e * 5;
        int row = min(i0 + e, NE - 1);
        inv_s[t] = g_inv[row * 5 + r];
    }

    float4 accA[8], accB[8];
    #pragma unroll
    for (int k = 0; k < 8; k++) { accA[k] = make_float4(0, 0, 0, 0); accB[k] = make_float4(0, 0, 0, 0); }

    for (int j0 = 0; j0 < NM; j0 += TJ) {
        __syncthreads();
        // lev tile: 64x32 bytes
        for (int t = tid; t < EB * TJ / 4; t += 256) {
            int e = t >> 3, c4 = t & 7;
            int row = min(i0 + e, NE - 1);
            *(uchar4*)(lev_s + e * TJ + c4 * 4) =
                *(const uchar4*)(g_lev + (size_t)row * NM + j0 + c4 * 4);
        }
        // Z tile: 5 x 32 x 256 floats, float4 coalesced
        for (int t4 = tid; t4 < 5 * TJ * 64; t4 += 256) {
            int ri = t4 >> 11;       // 2048 float4 per relation
            int q = t4 & 2047;
            int jj = q >> 6, c4 = q & 63;
            ((float4*)Zs)[(ri * TJ + jj) * 64 + c4] =
                *(const float4*)(g_Z + ((size_t)ri * NM + j0 + jj) * 256 + c4 * 4);
        }
        __syncthreads();

        for (int jj = 0; jj < TJ; jj++) {
            int lvA = lev_s[eA * TJ + jj];
            if (lvA) {
                float iv = inv_s[eA * 5 + lvA - 1];
                const float4* z = (const float4*)(Zs + ((lvA - 1) * TJ + jj) * 256) + cg;
                #pragma unroll
                for (int k = 0; k < 8; k++) {
                    float4 zz = z[k * 8];
                    accA[k].x += iv * zz.x; accA[k].y += iv * zz.y;
                    accA[k].z += iv * zz.z; accA[k].w += iv * zz.w;
                }
            }
            int lvB = lev_s[eBt * TJ + jj];
            if (lvB) {
                float iv = inv_s[eBt * 5 + lvB - 1];
                const float4* z = (const float4*)(Zs + ((lvB - 1) * TJ + jj) * 256) + cg;
                #pragma unroll
                for (int k = 0; k < 8; k++) {
                    float4 zz = z[k * 8];
                    accB[k].x += iv * zz.x; accB[k].y += iv * zz.y;
                    accB[k].z += iv * zz.z; accB[k].w += iv * zz.w;
                }
            }
        }
    }

    // ---- epilogue: reuse Zs as sAgg[64][260] then sE1[64][132] (padded strides) ----
    __syncthreads();
    float* sAgg = Zs;                 // 64*260 = 16640 floats
    float* sE1 = Zs + EB * 260;       // 64*132 =  8448 floats (total 25088 < 40960)
    #pragma unroll
    for (int k = 0; k < 8; k++) {
        *(float4*)(sAgg + eA * 260 + cg * 4 + k * 32) = accA[k];
        *(float4*)(sAgg + eBt * 260 + cg * 4 + k * 32) = accB[k];
    }
    __syncthreads();
    // e1 = relu(ebase + agg1)
    for (int t = tid; t < EB * D; t += 256) {
        int e = t >> 7, kk = t & 127;
        int row = min(i0 + e, NE - 1);
        float v = g_ebase[(size_t)row * D + kk] + sAgg[e * 260 + kk];
        sE1[e * 132 + kk] = fmaxf(v, 0.0f);
    }
    __syncthreads();
    // out = e1 @ root2 + agg2 + b2   (16 cols per thread per entity)
    int c0 = cg * 16;
    float4 oA[4], oB[4];
    #pragma unroll
    for (int q = 0; q < 4; q++) {
        float4 bb = *(const float4*)(b2 + c0 + q * 4);
        float4 gA = *(const float4*)(sAgg + eA * 260 + 128 + c0 + q * 4);
        float4 gB = *(const float4*)(sAgg + eBt * 260 + 128 + c0 + q * 4);
        oA[q] = make_float4(bb.x + gA.x, bb.y + gA.y, bb.z + gA.z, bb.w + gA.w);
        oB[q] = make_float4(bb.x + gB.x, bb.y + gB.y, bb.z + gB.z, bb.w + gB.w);
    }
    #pragma unroll 4
    for (int kk = 0; kk < 128; kk++) {
        float evA = sE1[eA * 132 + kk];
        float evB = sE1[eBt * 132 + kk];
        const float4* r2 = (const float4*)(root2 + kk * D + c0);
        #pragma unroll
        for (int q = 0; q < 4; q++) {
            float4 r = r2[q];
            oA[q].x += evA * r.x; oA[q].y += evA * r.y; oA[q].z += evA * r.z; oA[q].w += evA * r.w;
            oB[q].x += evB * r.x; oB[q].y += evB * r.y; oB[q].z += evB * r.z; oB[q].w += evB * r.w;
        }
    }
    if (i0 + eA < NE) {
        #pragma unroll
        for (int q = 0; q < 4; q++) *(float4*)(out + (size_t)(i0 + eA) * D + c0 + q * 4) = oA[q];
    }
    if (i0 + eBt < NE) {
        #pragma unroll
        for (int q = 0; q < 4; q++) *(float4*)(out + (size_t)(i0 + eBt) * D + c0 + q * 4) = oB[q];
    }
}

// ---------------- launch ----------------
extern "C" void kernel_launch(void* const* d_in, const int* in_sizes, int n_in,
                              void* d_out, int out_size) {
    const float* xe    = (const float*)d_in[0];
    const float* xm    = (const float*)d_in[1];
    const float* w     = (const float*)d_in[2];
    const float* W1    = (const float*)d_in[3];
    const float* root1 = (const float*)d_in[4];
    const float* b1    = (const float*)d_in[5];
    const float* W2    = (const float*)d_in[6];
    const float* root2 = (const float*)d_in[7];
    const float* b2    = (const float*)d_in[8];
    float* out = (float*)d_out;

    k_lev<<<NE, 256>>>(w);
    k_m1<<<NM / 8, 128>>>(xm, root1, b1);
    k_ebase<<<NE / 8, 128>>>(xe, root1, b1);
    k_Z<<<dim3(NM / 8, 5), 256>>>(xm, W1, W2);

    cudaFuncSetAttribute(k_main, cudaFuncAttributeMaxDynamicSharedMemorySize, SM_MAIN);
    k_main<<<(NE + EB - 1) / EB, 256, SM_MAIN>>>(root2, b2, out);
}

// round 5
// speedup vs baseline: 1.8138x; 1.8138x over previous
#include <cuda_runtime.h>
#include <cstdint>

#define NE 10000
#define NM 2048
#define D  128
#define NEP 10112            // 79 * 128, padded entity count

// ======================= device scratch (no allocations allowed) ============
__device__ unsigned char g_lev[(size_t)NE * NM];   // 0 = no edge, 1..5 relation
__device__ float g_inv[NE * 5];
__device__ float g_m1[NM * D];
__device__ float g_Zt[(size_t)5 * 256 * NM];       // [r][n][j]  (K-major B)
__device__ float g_ebase[(size_t)NE * D];
__device__ float g_part[(size_t)2 * NEP * 256];    // K-split partials

// ======================= small PTX helpers ============
#define CP_ASYNC16(s, g) asm volatile("cp.async.cg.shared.global [%0], [%1], 16;" :: "r"(s), "l"(g))
#define CP_COMMIT()      asm volatile("cp.async.commit_group;" ::: "memory")
#define CP_WAIT0()       asm volatile("cp.async.wait_group 0;" ::: "memory")

__device__ __forceinline__ uint32_t smem_u32(const void* p) {
    uint32_t a;
    asm("{ .reg .u64 t; cvta.to.shared.u64 t, %1; cvt.u32.u64 %0, t; }" : "=r"(a) : "l"(p));
    return a;
}

__device__ __forceinline__ void mma_tf32(float* d, const uint32_t* a, const uint32_t* b) {
    asm volatile(
        "mma.sync.aligned.m16n8k8.row.col.f32.tf32.tf32.f32 "
        "{%0,%1,%2,%3}, {%4,%5,%6,%7}, {%8,%9}, {%0,%1,%2,%3};"
        : "+f"(d[0]), "+f"(d[1]), "+f"(d[2]), "+f"(d[3])
        : "r"(a[0]), "r"(a[1]), "r"(a[2]), "r"(a[3]), "r"(b[0]), "r"(b[1]));
}

// ======================= kernel 1: levels + inverse counts ===================
__global__ void k_lev(const float* __restrict__ w) {
    int i = blockIdx.x;
    __shared__ int scnt[5];
    if (threadIdx.x < 5) scnt[threadIdx.x] = 0;
    __syncthreads();
    int cnt[5] = {0, 0, 0, 0, 0};
    const float* wr = w + (size_t)i * NM;
    unsigned char* lr = g_lev + (size_t)i * NM;
    for (int j = threadIdx.x; j < NM; j += 256) {
        float v = wr[j];
        int lv = (int)ceilf(v * 6.0f) - 1;
        int o = (lv >= 1 && lv <= 5) ? lv : 0;
        lr[j] = (unsigned char)o;
        if (o) cnt[o - 1]++;
    }
    #pragma unroll
    for (int r = 0; r < 5; r++) {
        int v = cnt[r];
        #pragma unroll
        for (int off = 16; off; off >>= 1) v += __shfl_down_sync(0xffffffffu, v, off);
        if ((threadIdx.x & 31) == 0) atomicAdd(&scnt[r], v);
    }
    __syncthreads();
    if (threadIdx.x < 5) {
        int c = scnt[threadIdx.x];
        g_inv[i * 5 + threadIdx.x] = (c > 0) ? 1.0f / (float)c : 0.0f;
    }
}

// ======================= kernel 2: m1 = relu(x_m @ root1 + b1) ===============
__global__ void k_m1(const float* __restrict__ xm, const float* __restrict__ root1,
                     const float* __restrict__ b1) {
    int j0 = blockIdx.x * 8;
    int c = threadIdx.x;
    __shared__ float xs[8][128];
    for (int t = c; t < 8 * 128; t += 128) xs[t >> 7][t & 127] = xm[(size_t)(j0 + (t >> 7)) * D + (t & 127)];
    __syncthreads();
    float a[8] = {0, 0, 0, 0, 0, 0, 0, 0};
    #pragma unroll 4
    for (int k = 0; k < 128; k++) {
        float wv = root1[k * D + c];
        #pragma unroll
        for (int e = 0; e < 8; e++) a[e] += xs[e][k] * wv;
    }
    float bb = b1[c];
    #pragma unroll
    for (int e = 0; e < 8; e++) g_m1[(size_t)(j0 + e) * D + c] = fmaxf(a[e] + bb, 0.0f);
}

// ======================= kernel 3: ebase = x_e @ root1 + b1 ==================
__global__ void k_ebase(const float* __restrict__ xe, const float* __restrict__ root1,
                        const float* __restrict__ b1) {
    int i0 = blockIdx.x * 8;
    int c = threadIdx.x;
    __shared__ float xs[8][128];
    for (int t = c; t < 8 * 128; t += 128) xs[t >> 7][t & 127] = xe[(size_t)(i0 + (t >> 7)) * D + (t & 127)];
    __syncthreads();
    float a[8] = {0, 0, 0, 0, 0, 0, 0, 0};
    #pragma unroll 4
    for (int k = 0; k < 128; k++) {
        float wv = root1[k * D + c];
        #pragma unroll
        for (int e = 0; e < 8; e++) a[e] += xs[e][k] * wv;
    }
    float bb = b1[c];
    #pragma unroll
    for (int e = 0; e < 8; e++) g_ebase[(size_t)(i0 + e) * D + c] = a[e] + bb;
}

// ======================= kernel 4: Zt[r][n][j] = cat(x_m@W1[r+1], m1@W2[r+1])^T
__global__ void k_Z(const float* __restrict__ xm, const float* __restrict__ W1,
                    const float* __restrict__ W2) {
    int ri = blockIdx.y;
    int j0 = blockIdx.x * 16;
    __shared__ float xs[16][128], ms[16][128];
    for (int t = threadIdx.x; t < 16 * 128; t += 256) {
        int e = t >> 7, k = t & 127;
        xs[e][k] = xm[(size_t)(j0 + e) * D + k];
        ms[e][k] = g_m1[(size_t)(j0 + e) * D + k];
    }
    __syncthreads();
    int c = threadIdx.x;
    int cc = c & 127;
    const float* W = ((c < 128) ? W1 : W2) + (size_t)(ri + 1) * D * D;
    const float(*S)[128] = (c < 128) ? xs : ms;
    float a[16];
    #pragma unroll
    for (int e = 0; e < 16; e++) a[e] = 0.0f;
    #pragma unroll 4
    for (int k = 0; k < 128; k++) {
        float wv = W[k * D + cc];
        #pragma unroll
        for (int e = 0; e < 16; e++) a[e] += S[e][k] * wv;
    }
    float* dst = g_Zt + ((size_t)ri * 256 + c) * NM + j0;
    #pragma unroll
    for (int e = 0; e < 16; e++) dst[e] = a[e];
}

// ======================= kernel 5: mma.sync tf32 GEMM (on-the-fly A) =========
// grid (79, 2, 2): x = M tile (128), y = N half (128 of 256), z = K half (5120)
// 512 threads, 16 warps in 4x4 (wm, wn), warp tile 32x32.
constexpr int KTILE = 32;
constexpr int KHALF = 5120;
constexpr int KITERS = KHALF / KTILE;       // 160
constexpr int ASTRIDE = 36;                 // floats per SMEM row (pad for banks)
constexpr int ATILE_F = 128 * ASTRIDE;      // 4608 floats
constexpr int SM_MMA_BYTES = 4 * ATILE_F * 4;  // A0,B0,A1,B1 = 73728 B

__global__ __launch_bounds__(512, 1) void k_mma() {
    extern __shared__ float smem[];
    float* As[2] = { smem,               smem + 2 * ATILE_F };
    float* Bs[2] = { smem + ATILE_F,     smem + 3 * ATILE_F };

    int tid = threadIdx.x;
    int wid = tid >> 5, lane = tid & 31;
    int gid = lane >> 2, t4 = lane & 3;
    int wm = wid & 3, wn = wid >> 2;

    int i0 = blockIdx.x * 128;
    int n0g = blockIdx.y * 128;          // column offset into Zt's 256 outputs
    int kbase = blockIdx.z * KHALF;

    // A-build role: row m = tid>>2, 8-byte chunk q = tid&3
    int am = tid >> 2, aq = tid & 3;
    int mrow = min(i0 + am, NE - 1);
    const unsigned char* levrow = g_lev + (size_t)mrow * NM;
    float inv5[5];
    #pragma unroll
    for (int r = 0; r < 5; r++) inv5[r] = g_inv[mrow * 5 + r];

    auto issueB = [&](int s, int r, int j0) {
        uint32_t sb = smem_u32(Bs[s]);
        #pragma unroll
        for (int h = 0; h < 2; h++) {
            int c = tid + h * 512;
            int n = c >> 3, ch = c & 7;
            uint32_t sa = sb + (uint32_t)(n * ASTRIDE + ch * 4) * 4u;
            const float* g = g_Zt + ((size_t)r * 256 + n0g + n) * NM + j0 + ch * 4;
            CP_ASYNC16(sa, g);
        }
        CP_COMMIT();
    };
    auto buildA = [&](int s, int r, int j0) {
        uint2 u = *(const uint2*)(levrow + j0 + aq * 8);
        unsigned char bts[8];
        *(uint2*)bts = u;
        float iv = inv5[r];
        unsigned char rv = (unsigned char)(r + 1);
        float4 v0, v1;
        v0.x = (bts[0] == rv) ? iv : 0.0f; v0.y = (bts[1] == rv) ? iv : 0.0f;
        v0.z = (bts[2] == rv) ? iv : 0.0f; v0.w = (bts[3] == rv) ? iv : 0.0f;
        v1.x = (bts[4] == rv) ? iv : 0.0f; v1.y = (bts[5] == rv) ? iv : 0.0f;
        v1.z = (bts[6] == rv) ? iv : 0.0f; v1.w = (bts[7] == rv) ? iv : 0.0f;
        float* dst = As[s] + am * ASTRIDE + aq * 8;
        *(float4*)dst = v0;
        *(float4*)(dst + 4) = v1;
    };

    float dacc[2][4][4];
    #pragma unroll
    for (int mi = 0; mi < 2; mi++)
        #pragma unroll
        for (int ni = 0; ni < 4; ni++)
            #pragma unroll
            for (int q = 0; q < 4; q++) dacc[mi][ni][q] = 0.0f;

    {
        int kg = kbase;
        issueB(0, kg >> 11, kg & 2047);
        buildA(0, kg >> 11, kg & 2047);
    }

    for (int it = 0; it < KITERS; it++) {
        int s = it & 1;
        CP_WAIT0();
        __syncthreads();
        if (it + 1 < KITERS) {
            int kg = kbase + (it + 1) * KTILE;
            issueB(s ^ 1, kg >> 11, kg & 2047);
            buildA(s ^ 1, kg >> 11, kg & 2047);
        }

        const float* A = As[s];
        const float* B = Bs[s];
        int ra = wm * 32 + gid;
        int nb = wn * 32 + gid;
        #pragma unroll
        for (int kk = 0; kk < 4; kk++) {
            int c = kk * 8 + t4;
            uint32_t af[2][4], bf[4][2];
            #pragma unroll
            for (int mi = 0; mi < 2; mi++) {
                int r = ra + mi * 16;
                af[mi][0] = __float_as_uint(A[r * ASTRIDE + c]);
                af[mi][1] = __float_as_uint(A[(r + 8) * ASTRIDE + c]);
                af[mi][2] = __float_as_uint(A[r * ASTRIDE + c + 4]);
                af[mi][3] = __float_as_uint(A[(r + 8) * ASTRIDE + c + 4]);
            }
            #pragma unroll
            for (int ni = 0; ni < 4; ni++) {
                int n = nb + ni * 8;
                bf[ni][0] = __float_as_uint(B[n * ASTRIDE + c]);
                bf[ni][1] = __float_as_uint(B[n * ASTRIDE + c + 4]);
            }
            #pragma unroll
            for (int mi = 0; mi < 2; mi++)
                #pragma unroll
                for (int ni = 0; ni < 4; ni++)
                    mma_tf32(dacc[mi][ni], af[mi], bf[ni]);
        }
        __syncthreads();
    }

    float* dst = g_part + (size_t)blockIdx.z * NEP * 256;
    #pragma unroll
    for (int mi = 0; mi < 2; mi++) {
        int r0 = i0 + wm * 32 + mi * 16 + gid;
        #pragma unroll
        for (int ni = 0; ni < 4; ni++) {
            int cn = n0g + wn * 32 + ni * 8 + 2 * t4;
            *(float2*)(dst + (size_t)r0 * 256 + cn) = make_float2(dacc[mi][ni][0], dacc[mi][ni][1]);
            *(float2*)(dst + (size_t)(r0 + 8) * 256 + cn) = make_float2(dacc[mi][ni][2], dacc[mi][ni][3]);
        }
    }
}

// ======================= kernel 6: reduce partials + both conv epilogues =====
// 64 entities per block, 256 threads: pe = tid>>3 in [0,31], entities 2pe, 2pe+1.
constexpr int SM_EPI_BYTES = 64 * 132 * 4;
__global__ __launch_bounds__(256, 1) void k_epi(const float* __restrict__ root2,
                                                const float* __restrict__ b2,
                                                float* __restrict__ out) {
    extern __shared__ float sE1[];   // [64][132]
    int i0 = blockIdx.x * 64;
    int tid = threadIdx.x;

    // e1 = relu(ebase + agg1)
    for (int idx = tid; idx < 64 * 32; idx += 256) {
        int e = idx >> 5, q = idx & 31;
        int i = i0 + e;
        float4 v;
        if (i < NE) {
            float4 p0 = *(const float4*)(g_part + (size_t)i * 256 + q * 4);
            float4 p1 = *(const float4*)(g_part + ((size_t)NEP + i) * 256 + q * 4);
            float4 eb = *(const float4*)(g_ebase + (size_t)i * D + q * 4);
            v.x = fmaxf(p0.x + p1.x + eb.x, 0.0f);
            v.y = fmaxf(p0.y + p1.y + eb.y, 0.0f);
            v.z = fmaxf(p0.z + p1.z + eb.z, 0.0f);
            v.w = fmaxf(p0.w + p1.w + eb.w, 0.0f);
        } else {
            v = make_float4(0, 0, 0, 0);
        }
        *(float4*)(sE1 + e * 132 + q * 4) = v;
    }
    __syncthreads();

    // out = e1 @ root2 + agg2 + b2 : 2 entities x 16 cols per thread
    int pe = tid >> 3, cg = tid & 7;
    int eA = pe * 2, eB = pe * 2 + 1;
    int iA = i0 + eA, iB = i0 + eB;
    int c0 = cg * 16;
    float4 oA[4], oB[4];
    #pragma unroll
    for (int q = 0; q < 4; q++) {
        float4 bb = *(const float4*)(b2 + c0 + q * 4);
        float4 gA = make_float4(0, 0, 0, 0), gB = make_float4(0, 0, 0, 0);
        if (iA < NE) {
            float4 a0 = *(const float4*)(g_part + (size_t)iA * 256 + 128 + c0 + q * 4);
            float4 a1 = *(const float4*)(g_part + ((size_t)NEP + iA) * 256 + 128 + c0 + q * 4);
            gA = make_float4(a0.x + a1.x, a0.y + a1.y, a0.z + a1.z, a0.w + a1.w);
        }
        if (iB < NE) {
            float4 a0 = *(const float4*)(g_part + (size_t)iB * 256 + 128 + c0 + q * 4);
            float4 a1 = *(const float4*)(g_part + ((size_t)NEP + iB) * 256 + 128 + c0 + q * 4);
            gB = make_float4(a0.x + a1.x, a0.y + a1.y, a0.z + a1.z, a0.w + a1.w);
        }
        oA[q] = make_float4(bb.x + gA.x, bb.y + gA.y, bb.z + gA.z, bb.w + gA.w);
        oB[q] = make_float4(bb.x + gB.x, bb.y + gB.y, bb.z + gB.z, bb.w + gB.w);
    }
    #pragma unroll 4
    for (int kk = 0; kk < 128; kk++) {
        float evA = sE1[eA * 132 + kk];
        float evB = sE1[eB * 132 + kk];
        const float4* r2 = (const float4*)(root2 + kk * D + c0);
        #pragma unroll
        for (int q = 0; q < 4; q++) {
            float4 r = r2[q];
            oA[q].x += evA * r.x; oA[q].y += evA * r.y; oA[q].z += evA * r.z; oA[q].w += evA * r.w;
            oB[q].x += evB * r.x; oB[q].y += evB * r.y; oB[q].z += evB * r.z; oB[q].w += evB * r.w;
        }
    }
    if (iA < NE) {
        #pragma unroll
        for (int q = 0; q < 4; q++) *(float4*)(out + (size_t)iA * D + c0 + q * 4) = oA[q];
    }
    if (iB < NE) {
        #pragma unroll
        for (int q = 0; q < 4; q++) *(float4*)(out + (size_t)iB * D + c0 + q * 4) = oB[q];
    }
}

// ======================= launch =======================
extern "C" void kernel_launch(void* const* d_in, const int* in_sizes, int n_in,
                              void* d_out, int out_size) {
    const float* xe    = (const float*)d_in[0];
    const float* xm    = (const float*)d_in[1];
    const float* w     = (const float*)d_in[2];
    const float* W1    = (const float*)d_in[3];
    const float* root1 = (const float*)d_in[4];
    const float* b1    = (const float*)d_in[5];
    const float* W2    = (const float*)d_in[6];
    const float* root2 = (const float*)d_in[7];
    const float* b2    = (const float*)d_in[8];
    float* out = (float*)d_out;

    k_lev<<<NE, 256>>>(w);
    k_m1<<<NM / 8, 128>>>(xm, root1, b1);
    k_ebase<<<NE / 8, 128>>>(xe, root1, b1);
    k_Z<<<dim3(NM / 16, 5), 256>>>(xm, W1, W2);

    cudaFuncSetAttribute(k_mma, cudaFuncAttributeMaxDynamicSharedMemorySize, SM_MMA_BYTES);
    k_mma<<<dim3(79, 2, 2), 512, SM_MMA_BYTES>>>();

    cudaFuncSetAttribute(k_epi, cudaFuncAttributeMaxDynamicSharedMemorySize, SM_EPI_BYTES);
    k_epi<<<NEP / 64, 256, SM_EPI_BYTES>>>(root2, b2, out);
}